// round 2
// baseline (speedup 1.0000x reference)
#include <cuda_runtime.h>
#include <cstdint>

#define NS 13824            // D*H*W = 24*24*24
#define NB 2                // batch
#define NC 64               // channels
#define NVOX (NB * NS)      // 27648 voxels total

// Scratch: q (pre-scaled by hd^-0.5), k, v in voxel-major layout [n][c]
__device__ float g_q[NVOX * NC];
__device__ float g_k[NVOX * NC];
__device__ float g_v[NVOX * NC];

typedef unsigned long long u64;

// ---- packed f32x2 helpers (sm_100+: 2x fp32 FMA throughput) -----------------
__device__ __forceinline__ u64 pack2(float lo, float hi) {
    u64 r; asm("mov.b64 %0,{%1,%2};" : "=l"(r) : "f"(lo), "f"(hi)); return r;
}
__device__ __forceinline__ float2 unpack2(u64 v) {
    float2 r; asm("mov.b64 {%0,%1},%2;" : "=f"(r.x), "=f"(r.y) : "l"(v)); return r;
}
__device__ __forceinline__ u64 fma2(u64 a, u64 b, u64 c) {
    u64 d; asm("fma.rn.f32x2 %0,%1,%2,%3;" : "=l"(d) : "l"(a), "l"(b), "l"(c)); return d;
}
__device__ __forceinline__ u64 add2(u64 a, u64 b) {
    u64 d; asm("add.rn.f32x2 %0,%1,%2;" : "=l"(d) : "l"(a), "l"(b)); return d;
}

// ---------------------------------------------------------------------------
// Kernel 1: QKV projection. One block = 64 consecutive voxels of one batch.
// Packed f32x2 accumulation across voxel pairs (8 FMA2/j vs 16 FFMA/j).
// ---------------------------------------------------------------------------
__global__ __launch_bounds__(256) void k_proj(
    const float* __restrict__ x,
    const float* __restrict__ Wq, const float* __restrict__ bq,
    const float* __restrict__ Wk, const float* __restrict__ bk,
    const float* __restrict__ Wv, const float* __restrict__ bv)
{
    __shared__ __align__(16) float WT[64 * 66];   // WT[j*66 + c] = W[c][j]
    __shared__ __align__(16) float Xs[64 * 64];   // Xs[j*64 + t] = x[b][j][s0+t]
    __shared__ float bs[64];

    const int tid  = threadIdx.x;
    const int tile = blockIdx.x;              // 0..431
    const int bb   = tile / (NS / 64);
    const int s0   = (tile % (NS / 64)) * 64;

    const float* xb = x + (long)bb * NC * NS + s0;

#pragma unroll
    for (int k = 0; k < 16; k++) {
        int idx = tid + k * 256;
        int c = idx >> 6, u = idx & 63;
        Xs[c * 64 + u] = xb[(long)c * NS + u];
    }

    const int lane = tid & 31;
    const int wid  = tid >> 5;
    const int c0   = lane * 2;     // channel pair this thread owns
    const int t0   = wid * 8;      // 8 voxels this thread owns

    const float* Wsrc[3] = {Wq, Wk, Wv};
    const float* bsrc[3] = {bq, bk, bv};
    float* gout[3];
    gout[0] = g_q; gout[1] = g_k; gout[2] = g_v;

#pragma unroll
    for (int m = 0; m < 3; m++) {
        __syncthreads();
        const float* W = Wsrc[m];
#pragma unroll
        for (int k2 = 0; k2 < 16; k2++) {
            int idx = tid + k2 * 256;
            int c = idx >> 6, j = idx & 63;
            WT[j * 66 + c] = W[idx];
        }
        if (tid < 64) bs[tid] = bsrc[m][tid];
        __syncthreads();

        const float bias0 = bs[c0], bias1 = bs[c0 + 1];
        u64 accA[4], accB[4];    // ch c0 / c0+1, each over 8 voxels (4 pairs)
#pragma unroll
        for (int v = 0; v < 4; v++) {
            accA[v] = pack2(bias0, bias0);
            accB[v] = pack2(bias1, bias1);
        }

#pragma unroll 4
        for (int j = 0; j < 64; j++) {
            float2 w = *(const float2*)&WT[j * 66 + c0];
            u64 wx = pack2(w.x, w.x);
            u64 wy = pack2(w.y, w.y);
            const u64* xp = (const u64*)&Xs[j * 64 + t0];
            u64 x0 = xp[0], x1 = xp[1], x2 = xp[2], x3 = xp[3];
            accA[0] = fma2(wx, x0, accA[0]);
            accA[1] = fma2(wx, x1, accA[1]);
            accA[2] = fma2(wx, x2, accA[2]);
            accA[3] = fma2(wx, x3, accA[3]);
            accB[0] = fma2(wy, x0, accB[0]);
            accB[1] = fma2(wy, x1, accB[1]);
            accB[2] = fma2(wy, x2, accB[2]);
            accB[3] = fma2(wy, x3, accB[3]);
        }

        const float scale = (m == 0) ? 0.25f : 1.0f;   // hd^-0.5
        float* g = gout[m];
#pragma unroll
        for (int v = 0; v < 4; v++) {
            float2 a = unpack2(accA[v]);
            float2 b = unpack2(accB[v]);
            int n = bb * NS + s0 + t0 + 2 * v;
            float2 o0; o0.x = a.x * scale; o0.y = b.x * scale;
            float2 o1; o1.x = a.y * scale; o1.y = b.y * scale;
            *(float2*)&g[(long)n * NC + c0]        = o0;
            *(float2*)&g[(long)(n + 1) * NC + c0]  = o1;
        }
    }
}

// ---------------------------------------------------------------------------
// Kernel 2: 3x3x3 local attention + residual.
// Thread = (voxel, head): full 16-dim head in registers. No shuffles, one
// exp per (neighbor, head). Softmax without max-subtraction (shift-invariant;
// logits are O(1) here, exp cannot overflow). Fully unrolled neighbor loop
// -> compile-time address offsets. Packed f32x2 FMA for dot and P.V.
// Block = 256 threads = 64 voxels x 4 heads; smem transpose for coalesced
// channel-major output + residual.
// ---------------------------------------------------------------------------
__global__ __launch_bounds__(256) void k_attn(
    const float* __restrict__ x, float* __restrict__ out)
{
    __shared__ float hs[64 * 65];

    const int tid  = threadIdx.x;
    const int vloc = tid >> 2;          // voxel slot in block [0,64)
    const int head = tid & 3;

    const int n0 = blockIdx.x * 64;     // NS % 64 == 0, never crosses batch
    const int bb = n0 / NS;
    const int s0 = n0 % NS;
    const int s  = s0 + vloc;
    const int d = s / 576, h = (s / 24) % 24, w = s % 24;
    const int n = bb * NS + s;

    const long base = (long)n * NC + head * 16;
    const ulonglong2* qp = (const ulonglong2*)(g_q + base);
    u64 q[8];
#pragma unroll
    for (int i = 0; i < 4; i++) {
        ulonglong2 t = qp[i];
        q[2 * i] = t.x; q[2 * i + 1] = t.y;
    }
    const float* kb = g_k + base;
    const float* vb = g_v + base;

    const bool okd[3] = {d > 0, true, d < 23};
    const bool okh[3] = {h > 0, true, h < 23};
    const bool okw[3] = {w > 0, true, w < 23};

    u64 acc[8];
#pragma unroll
    for (int i = 0; i < 8; i++) acc[i] = 0ull;   // (0.0f, 0.0f)
    float lsum = 0.0f;

#pragma unroll
    for (int di = 0; di < 3; di++) {
#pragma unroll
        for (int hi = 0; hi < 3; hi++) {
#pragma unroll
            for (int wi = 0; wi < 3; wi++) {
                if (okd[di] & okh[hi] & okw[wi]) {
                    const int off = ((di - 1) * 576 + (hi - 1) * 24 + (wi - 1)) * NC;
                    const ulonglong2* kp = (const ulonglong2*)(kb + off);
                    ulonglong2 k0 = kp[0], k1 = kp[1], k2 = kp[2], k3 = kp[3];
                    u64 t0 = fma2(q[0], k0.x, 0ull);
                    u64 t1 = fma2(q[1], k0.y, 0ull);
                    t0 = fma2(q[2], k1.x, t0);
                    t1 = fma2(q[3], k1.y, t1);
                    t0 = fma2(q[4], k2.x, t0);
                    t1 = fma2(q[5], k2.y, t1);
                    t0 = fma2(q[6], k3.x, t0);
                    t1 = fma2(q[7], k3.y, t1);
                    float2 ts = unpack2(add2(t0, t1));
                    float p = __expf(ts.x + ts.y);
                    lsum += p;
                    u64 p2 = pack2(p, p);
                    const ulonglong2* vp = (const ulonglong2*)(vb + off);
                    ulonglong2 v0 = vp[0], v1 = vp[1], v2 = vp[2], v3 = vp[3];
                    acc[0] = fma2(p2, v0.x, acc[0]);
                    acc[1] = fma2(p2, v0.y, acc[1]);
                    acc[2] = fma2(p2, v1.x, acc[2]);
                    acc[3] = fma2(p2, v1.y, acc[3]);
                    acc[4] = fma2(p2, v2.x, acc[4]);
                    acc[5] = fma2(p2, v2.y, acc[5]);
                    acc[6] = fma2(p2, v3.x, acc[6]);
                    acc[7] = fma2(p2, v3.y, acc[7]);
                } else {
                    lsum += 1.0f;   // exp(0) with zero-padded k,v
                }
            }
        }
    }

    const float inv = 1.0f / lsum;
    const int cbase = head * 16;
#pragma unroll
    for (int i = 0; i < 8; i++) {
        float2 a = unpack2(acc[i]);
        hs[(cbase + 2 * i)     * 65 + vloc] = a.x * inv;
        hs[(cbase + 2 * i + 1) * 65 + vloc] = a.y * inv;
    }
    __syncthreads();

    // Coalesced channel-major output with residual add
#pragma unroll
    for (int k = 0; k < 16; k++) {
        int idx = tid + k * 256;
        int c = idx >> 6, t = idx & 63;
        long gi = ((long)bb * NC + c) * NS + s0 + t;
        out[gi] = hs[c * 65 + t] + x[gi];
    }
}

// ---------------------------------------------------------------------------
extern "C" void kernel_launch(void* const* d_in, const int* in_sizes, int n_in,
                              void* d_out, int out_size)
{
    const float* x  = (const float*)d_in[0];
    // d_in[1] = cemb (unused by reference forward)
    const float* Wq = (const float*)d_in[2];
    const float* bq = (const float*)d_in[3];
    const float* Wk = (const float*)d_in[4];
    const float* bk = (const float*)d_in[5];
    const float* Wv = (const float*)d_in[6];
    const float* bv = (const float*)d_in[7];
    float* out = (float*)d_out;

    k_proj<<<NVOX / 64, 256>>>(x, Wq, bq, Wk, bk, Wv, bv);
    k_attn<<<NVOX / 64, 256>>>(x, out);
}

// round 3
// speedup vs baseline: 1.4106x; 1.4106x over previous
#include <cuda_runtime.h>
#include <cstdint>

#define NS 13824            // D*H*W = 24*24*24
#define NB 2                // batch
#define NC 64               // channels
#define NVOX (NB * NS)      // 27648 voxels total

// Scratch: q (pre-scaled by hd^-0.5), k, v in voxel-major layout [n][c]
__device__ float g_q[NVOX * NC];
__device__ float g_k[NVOX * NC];
__device__ float g_v[NVOX * NC];

typedef unsigned long long u64;

// ---- packed f32x2 helpers (sm_100+: 2x fp32 FMA throughput) -----------------
__device__ __forceinline__ u64 pack2(float lo, float hi) {
    u64 r; asm("mov.b64 %0,{%1,%2};" : "=l"(r) : "f"(lo), "f"(hi)); return r;
}
__device__ __forceinline__ float2 unpack2(u64 v) {
    float2 r; asm("mov.b64 {%0,%1},%2;" : "=f"(r.x), "=f"(r.y) : "l"(v)); return r;
}
__device__ __forceinline__ u64 fma2(u64 a, u64 b, u64 c) {
    u64 d; asm("fma.rn.f32x2 %0,%1,%2,%3;" : "=l"(d) : "l"(a), "l"(b), "l"(c)); return d;
}

// ---------------------------------------------------------------------------
// Kernel 1: QKV projection. Block = 64 voxels of one batch, 8 warps.
// Warp tile = 32 channels x 16 voxels; lane tile = 4 channels x 4 voxels.
// Per j: one LDS.128 of W (conflict-free) + one LDS.128 of x (8-lane bcast)
// feeds 8 fma2 per lane -> LDS crossbar well under FMA2 pipe.
// ---------------------------------------------------------------------------
__global__ __launch_bounds__(256) void k_proj(
    const float* __restrict__ x,
    const float* __restrict__ Wq, const float* __restrict__ bq,
    const float* __restrict__ Wk, const float* __restrict__ bk,
    const float* __restrict__ Wv, const float* __restrict__ bv)
{
    __shared__ __align__(16) float WTs[64 * 68];   // WTs[j*68 + c] = W[c][j]
    __shared__ __align__(16) float Xs[64 * 64];    // Xs[j*64 + t] = x[b][j][s0+t]

    const int tid  = threadIdx.x;
    const int lane = tid & 31;
    const int wid  = tid >> 5;
    const int tile = blockIdx.x;               // 0..431
    const int bb   = tile / (NS / 64);
    const int s0   = (tile % (NS / 64)) * 64;

    const float* xb = x + (long)bb * NC * NS + s0;

    // x tile (coalesced, conflict-free writes)
#pragma unroll
    for (int k = 0; k < 16; k++) {
        int idx = tid + k * 256;
        int j = idx >> 6, u = idx & 63;
        Xs[j * 64 + u] = xb[(long)j * NS + u];
    }

    // lane tile coordinates
    const int c0  = (wid & 1) * 32 + (lane >> 2) * 4;      // 4 channels
    const int tv0 = (wid >> 1) * 16 + (lane & 3) * 4;      // 4 voxels

    const float* Wsrc[3] = {Wq, Wk, Wv};
    const float* bsrc[3] = {bq, bk, bv};
    float* gout[3];
    gout[0] = g_q; gout[1] = g_k; gout[2] = g_v;

#pragma unroll
    for (int m = 0; m < 3; m++) {
        __syncthreads();   // previous iteration done reading WTs (covers Xs 1st time)
        const float* W = Wsrc[m];
#pragma unroll
        for (int k2 = 0; k2 < 16; k2++) {
            int idx = tid + k2 * 256;
            int c = idx >> 6, j = idx & 63;
            WTs[j * 68 + c] = W[idx];          // transpose to [j][c]
        }
        __syncthreads();

        const float4 bv4 = *(const float4*)&bsrc[m][c0];
        u64 acc[4][2];     // [voxel][channel-pair]
#pragma unroll
        for (int t = 0; t < 4; t++) {
            acc[t][0] = pack2(bv4.x, bv4.y);
            acc[t][1] = pack2(bv4.z, bv4.w);
        }

#pragma unroll 8
        for (int j = 0; j < 64; j++) {
            ulonglong2 w = *(const ulonglong2*)&WTs[j * 68 + c0];   // (w0,w1),(w2,w3)
            float4 xv = *(const float4*)&Xs[j * 64 + tv0];          // 4 voxels
            u64 xd0 = pack2(xv.x, xv.x);
            u64 xd1 = pack2(xv.y, xv.y);
            u64 xd2 = pack2(xv.z, xv.z);
            u64 xd3 = pack2(xv.w, xv.w);
            acc[0][0] = fma2(w.x, xd0, acc[0][0]);
            acc[0][1] = fma2(w.y, xd0, acc[0][1]);
            acc[1][0] = fma2(w.x, xd1, acc[1][0]);
            acc[1][1] = fma2(w.y, xd1, acc[1][1]);
            acc[2][0] = fma2(w.x, xd2, acc[2][0]);
            acc[2][1] = fma2(w.y, xd2, acc[2][1]);
            acc[3][0] = fma2(w.x, xd3, acc[3][0]);
            acc[3][1] = fma2(w.y, xd3, acc[3][1]);
        }

        const float scale = (m == 0) ? 0.25f : 1.0f;   // hd^-0.5 = 16^-0.5
        float* g = gout[m];
#pragma unroll
        for (int t = 0; t < 4; t++) {
            float2 a = unpack2(acc[t][0]);
            float2 b = unpack2(acc[t][1]);
            int n = bb * NS + s0 + tv0 + t;
            float4 o;
            o.x = a.x * scale; o.y = a.y * scale;
            o.z = b.x * scale; o.w = b.y * scale;
            *(float4*)&g[(long)n * NC + c0] = o;
        }
    }
}

// ---------------------------------------------------------------------------
// Kernel 2: 3x3x3 local attention + residual.
// Voxel per 16 lanes; lane owns 4 contiguous channels (one LDG.128 per k/v
// per neighbor -> perfectly coalesced: warp reads 512B contiguous).
// Quad of lanes = one head; 2-shfl reduction completes the 16-dim dot.
// Single-pass softmax (shift-invariant, logits O(1)): zero-padded borders
// handled by zero-init + predicated loads -> exp(0)=1, zero v. No divergence,
// no per-neighbor index math (compile-time offsets).
// ---------------------------------------------------------------------------
__global__ __launch_bounds__(256) void k_attn(
    const float* __restrict__ x, float* __restrict__ out)
{
    __shared__ float hs[64 * 17];

    const int tid  = threadIdx.x;
    const int lane = tid & 31;
    const int wid  = tid >> 5;

    const int n0 = blockIdx.x * 16;      // 16 voxels per block
    const int bb = n0 / NS;
    const int s0 = n0 % NS;

    const int half = lane >> 4;
    const int l4   = lane & 15;
    const int vloc = wid * 2 + half;
    const int s    = s0 + vloc;
    const int d = s / 576, h = (s / 24) % 24, w = s % 24;
    const int c0 = l4 * 4;               // 4 channels; quad (l4>>2) = head
    const int n  = bb * NS + s;

    const long base = (long)n * NC + c0;
    const ulonglong2 qv = *(const ulonglong2*)(g_q + base);
    const u64 q01 = qv.x, q23 = qv.y;
    const float* kb = g_k + base;
    const float* vb = g_v + base;

    const bool okd[3] = {d > 0, true, d < 23};
    const bool okh[3] = {h > 0, true, h < 23};
    const bool okw[3] = {w > 0, true, w < 23};

    u64 acc01 = 0ull, acc23 = 0ull;
    float lsum = 0.0f;

#pragma unroll
    for (int di = 0; di < 3; di++) {
#pragma unroll
        for (int hi = 0; hi < 3; hi++) {
#pragma unroll
            for (int wi = 0; wi < 3; wi++) {
                const int off = ((di - 1) * 576 + (hi - 1) * 24 + (wi - 1)) * NC;
                u64 k01 = 0ull, k23 = 0ull, v01 = 0ull, v23 = 0ull;
                if (okd[di] & okh[hi] & okw[wi]) {
                    ulonglong2 kk = *(const ulonglong2*)(kb + off);
                    ulonglong2 vv = *(const ulonglong2*)(vb + off);
                    k01 = kk.x; k23 = kk.y; v01 = vv.x; v23 = vv.y;
                }
                u64 dd = fma2(q01, k01, 0ull);
                dd = fma2(q23, k23, dd);
                float2 df = unpack2(dd);
                float sc = df.x + df.y;
                sc += __shfl_xor_sync(0xffffffffu, sc, 1);
                sc += __shfl_xor_sync(0xffffffffu, sc, 2);
                float p = __expf(sc);     // padding: exp(0)=1 (matches reference)
                lsum += p;
                u64 p2 = pack2(p, p);
                acc01 = fma2(p2, v01, acc01);
                acc23 = fma2(p2, v23, acc23);
            }
        }
    }

    const float inv = 1.0f / lsum;
    {
        float2 a = unpack2(acc01);
        float2 b = unpack2(acc23);
        hs[(c0 + 0) * 17 + vloc] = a.x * inv;
        hs[(c0 + 1) * 17 + vloc] = a.y * inv;
        hs[(c0 + 2) * 17 + vloc] = b.x * inv;
        hs[(c0 + 3) * 17 + vloc] = b.y * inv;
    }
    __syncthreads();

    // Coalesced channel-major output with residual add
#pragma unroll
    for (int k = 0; k < 4; k++) {
        int idx = tid + k * 256;
        int c = idx >> 4, t = idx & 15;
        long gi = ((long)bb * NC + c) * NS + s0 + t;
        out[gi] = hs[c * 17 + t] + x[gi];
    }
}

// ---------------------------------------------------------------------------
extern "C" void kernel_launch(void* const* d_in, const int* in_sizes, int n_in,
                              void* d_out, int out_size)
{
    const float* x  = (const float*)d_in[0];
    // d_in[1] = cemb (unused by reference forward)
    const float* Wq = (const float*)d_in[2];
    const float* bq = (const float*)d_in[3];
    const float* Wk = (const float*)d_in[4];
    const float* bk = (const float*)d_in[5];
    const float* Wv = (const float*)d_in[6];
    const float* bv = (const float*)d_in[7];
    float* out = (float*)d_out;

    k_proj<<<NVOX / 64, 256>>>(x, Wq, bq, Wk, bk, Wv, bv);
    k_attn<<<NVOX / 16, 256>>>(x, out);
}